// round 3
// baseline (speedup 1.0000x reference)
#include <cuda_runtime.h>
#include <cuda_bf16.h>
#include <cstdint>

#define N_SAMP   262144
#define ZD       2
#define CTX      128
#define HID      128
#define TEMB     32
#define NSTEPS   50
#define SPB      64      // samples per block
#define NWARPS   16      // 8 diffusion-MLP warps + 8 cnf-MLP warps

// output layout: traj [51,N,2] | us [50,N,2] | times [51]
#define US_OFF    ((long long)(NSTEPS+1) * N_SAMP * ZD)
#define TAIL_OFF  (US_OFF + (long long)NSTEPS * N_SAMP * ZD)

// per-step precomputed constants
__device__ float g_twd[NSTEPS * HID];
__device__ float g_twc[NSTEPS * HID];
__device__ float g_dts[NSTEPS];
__device__ float g_coef[NSTEPS];

typedef unsigned long long u64;

__device__ __forceinline__ float fsilu(float x) {
    float e = __expf(-x);
    return __fdividef(x, 1.0f + e);
}
__device__ __forceinline__ u64 f2pack(float a, float b) {
    u64 r; asm("mov.b64 %0, {%1, %2};" : "=l"(r) : "f"(a), "f"(b)); return r;
}
__device__ __forceinline__ void f2unpack(u64 v, float& a, float& b) {
    asm("mov.b64 {%0, %1}, %2;" : "=f"(a), "=f"(b) : "l"(v));
}
__device__ __forceinline__ u64 ffma2(u64 a, u64 b, u64 c) {
    u64 d; asm("fma.rn.f32x2 %0, %1, %2, %3;" : "=l"(d) : "l"(a), "l"(b), "l"(c)); return d;
}
__device__ __forceinline__ u64 lds_u64(uint32_t addr) {
    u64 v; asm volatile("ld.shared.b64 %0, [%1];" : "=l"(v) : "r"(addr)); return v;
}

// ---------------------------------------------------------------------------
// Kernel A: per-step constants (temb @ W1_temb + b1, dt, diffusion coef) + times tail
// ---------------------------------------------------------------------------
__global__ void prep_kernel(const float* __restrict__ times,
                            const float* __restrict__ freqs,
                            const float* __restrict__ dW1, const float* __restrict__ db1,
                            const float* __restrict__ cW1, const float* __restrict__ cb1,
                            const float* __restrict__ log_diff,
                            float* __restrict__ out)
{
    __shared__ float temb[TEMB];
    int tid = threadIdx.x;  // 128 threads
    if (tid < NSTEPS + 1) out[TAIL_OFF + tid] = times[tid];
    float gb = log1pf(__expf(log_diff[0]));  // softplus
    for (int i = 0; i < NSTEPS; i++) {
        float t = times[i];
        __syncthreads();
        if (tid < TEMB / 2) {
            float a = 6.2831853071795864f * t * freqs[tid];
            temb[tid]            = sinf(a);
            temb[tid + TEMB / 2] = cosf(a);
        }
        __syncthreads();
        float ad = db1[tid], ac = cb1[tid];
#pragma unroll 8
        for (int m = 0; m < TEMB; m++) {
            float tv = temb[m];
            ad += tv * dW1[(ZD + CTX + m) * HID + tid];
            ac += tv * cW1[(ZD + CTX + m) * HID + tid];
        }
        g_twd[i * HID + tid] = ad;
        g_twc[i * HID + tid] = ac;
        if (tid == 0) {
            float dt = times[i + 1] - t;
            g_dts[i]  = dt;
            g_coef[i] = gb * (1.0f - t) * sqrtf(fmaxf(dt, 1e-12f));
        }
    }
}

// ---------------------------------------------------------------------------
// base = ctx @ W1[2:130] for one warp's 8 samples
// ---------------------------------------------------------------------------
__device__ __forceinline__ void compute_base(float* __restrict__ dst,
                                             const float* __restrict__ tmp,
                                             const float* __restrict__ W1,
                                             int wg, int l)
{
    float acc[8][4];
#pragma unroll
    for (int s8 = 0; s8 < 8; s8++)
#pragma unroll
        for (int c = 0; c < 4; c++) acc[s8][c] = 0.f;
#pragma unroll 2
    for (int r = 0; r < CTX; r++) {
        float w1v[4];
#pragma unroll
        for (int c = 0; c < 4; c++) w1v[c] = W1[(ZD + r) * HID + l + 32 * c];
#pragma unroll
        for (int s8 = 0; s8 < 8; s8++) {
            float a = tmp[(wg * 8 + s8) * HID + r];
#pragma unroll
            for (int c = 0; c < 4; c++) acc[s8][c] += a * w1v[c];
        }
    }
#pragma unroll
    for (int s8 = 0; s8 < 8; s8++)
#pragma unroll
        for (int c = 0; c < 4; c++)
            dst[(wg * 8 + s8) * HID + l + 32 * c] = acc[s8][c];
}

// ---------------------------------------------------------------------------
// Kernel B: persistent 50-step SDE. 512 threads / CTA, 64 samples.
// Warps 0-7: diffusion MLP (u), warps 8-15: cnf MLP (f). 8 samples per warp.
// SMEM: baseD(32K) baseC(32K) W2d(64K) W2c(64K) a1buf(32K) uf(2K) = 231424B.
// ---------------------------------------------------------------------------
__global__ void __launch_bounds__(512, 1)
sde_kernel(const float* __restrict__ z0,
           const float* __restrict__ pctx, const float* __restrict__ cctx,
           const float* __restrict__ noise,
           const float* __restrict__ dW1, const float* __restrict__ dW2,
           const float* __restrict__ db2, const float* __restrict__ dW3,
           const float* __restrict__ db3,
           const float* __restrict__ cW1, const float* __restrict__ cW2,
           const float* __restrict__ cb2, const float* __restrict__ cW3,
           const float* __restrict__ cb3,
           float* __restrict__ out)
{
    extern __shared__ float sm[];
    float* baseD = sm;                       // 64*128
    float* baseC = baseD + SPB * HID;        // 64*128
    float* sW2d  = baseC + SPB * HID;        // 128*128
    float* sW2c  = sW2d + HID * HID;         // 128*128
    u64*   a1buf = (u64*)(sW2c + HID * HID); // 16 warps * 256 u64
    float* uf    = (float*)(a1buf + NWARPS * 256); // 2 bufs * 2 mlp * 64 * 2

    int tid = threadIdx.x;
    int w = tid >> 5, l = tid & 31;
    int m  = w >> 3;      // 0 = diffusion MLP (u), 1 = cnf MLP (f)
    int wg = w & 7;       // sample group
    int blockBase = blockIdx.x * SPB;
    int sbase = blockBase + wg * 8;
    int myS = l >> 1, myD = l & 1;

    const float* W1 = m ? cW1 : dW1;

    // ---- phase 1: stage ctx tiles into W2 areas, compute base, then load W2 ----
    for (int idx = tid; idx < SPB * HID; idx += 512) {
        sW2d[idx] = pctx[(long long)blockBase * HID + idx];
        sW2c[idx] = cctx[(long long)blockBase * HID + idx];
    }
    __syncthreads();
    {
        const float* tmp = m ? sW2c : sW2d;
        float* dstBase   = m ? baseC : baseD;
        compute_base(dstBase, tmp, W1, wg, l);
    }
    __syncthreads();
    for (int idx = tid; idx < HID * HID; idx += 512) { sW2d[idx] = dW2[idx]; sW2c[idx] = cW2[idx]; }
    __syncthreads();

    // ---- per-lane constant weights in registers (single MLP) ----
    const float* W2s   = m ? sW2c : sW2d;
    const float* W3    = m ? cW3  : dW3;
    const float* b2    = m ? cb2  : db2;
    const float* b3    = m ? cb3  : db3;
    const float* twAll = m ? g_twc : g_twd;
    const float* bsw   = (m ? baseC : baseD) + wg * 8 * HID;

    float wzr[2][4], w3r[4][2], b2r[4];
#pragma unroll
    for (int c = 0; c < 4; c++) {
        int j = l + 32 * c;
        wzr[0][c] = W1[0 * HID + j];
        wzr[1][c] = W1[1 * HID + j];
        w3r[c][0] = W3[j * ZD + 0];
        w3r[c][1] = W3[j * ZD + 1];
        b2r[c]    = b2[j];
    }
    float b3_own = b3[myD];

    // ---- init z (owner lanes l<16 hold (s = l>>1, d = l&1)); cnf warps write traj[0] ----
    float z_own = 0.f;
    if (l < 16) {
        long long gs = sbase + myS;
        z_own = z0[gs * ZD + myD];
        if (m) out[gs * ZD + myD] = z_own;  // traj[0]
    }
    float zz[8][2];
#pragma unroll
    for (int s = 0; s < 8; s++) {
        zz[s][0] = __shfl_sync(0xffffffffu, z_own, 2 * s);
        zz[s][1] = __shfl_sync(0xffffffffu, z_own, 2 * s + 1);
    }

    uint32_t myA = (uint32_t)__cvta_generic_to_shared(a1buf + w * 256);

    // ---- 50-step loop ----
    for (int i = 0; i < NSTEPS; i++) {
        float twr[4];
#pragma unroll
        for (int c = 0; c < 4; c++) twr[c] = twAll[i * HID + l + 32 * c];

        u64 acc[4][4];
#pragma unroll
        for (int p = 0; p < 4; p++)
#pragma unroll
            for (int c = 0; c < 4; c++) acc[p][c] = 0ull;

#pragma unroll
        for (int ch = 0; ch < 2; ch++) {
            __syncwarp();
            // layer 1 (rank-2 update) + silu -> packed sample-pairs in a1buf
#pragma unroll
            for (int p = 0; p < 4; p++) {
#pragma unroll
                for (int t = 0; t < 2; t++) {
                    int kk = l + 32 * t;
                    int k  = ch * 64 + kk;
                    int c  = ch * 2 + t;
                    float twv = twr[c];
                    int s0 = 2 * p;
                    float h0 = bsw[s0 * HID + k] + twv
                             + zz[2 * p][0]     * wzr[0][c] + zz[2 * p][1]     * wzr[1][c];
                    float h1 = bsw[(s0 + 1) * HID + k] + twv
                             + zz[2 * p + 1][0] * wzr[0][c] + zz[2 * p + 1][1] * wzr[1][c];
                    a1buf[w * 256 + p * 64 + kk] = f2pack(fsilu(h0), fsilu(h1));
                }
            }
            __syncwarp();
            // layer 2: packed fp32x2 GEMM (8 samples x 128 j over 64 k)
#pragma unroll 4
            for (int kk = 0; kk < 64; kk++) {
                int k = ch * 64 + kk;
                u64 A[4];
#pragma unroll
                for (int p = 0; p < 4; p++) A[p] = lds_u64(myA + (p * 64 + kk) * 8);
                u64 B[4];
#pragma unroll
                for (int c = 0; c < 4; c++) {
                    float wv = W2s[k * HID + l + 32 * c];
                    B[c] = f2pack(wv, wv);
                }
#pragma unroll
                for (int p = 0; p < 4; p++)
#pragma unroll
                    for (int c = 0; c < 4; c++)
                        acc[p][c] = ffma2(A[p], B[c], acc[p][c]);
            }
        }

        // epilogue: silu(h2 + b2), layer-3 partials
        float rv[16];
#pragma unroll
        for (int j = 0; j < 16; j++) rv[j] = 0.f;
#pragma unroll
        for (int p = 0; p < 4; p++) {
#pragma unroll
            for (int c = 0; c < 4; c++) {
                float lo, hi;
                f2unpack(acc[p][c], lo, hi);
                lo = fsilu(lo + b2r[c]);
                hi = fsilu(hi + b2r[c]);
                rv[(2 * p) * 2 + 0]     += lo * w3r[c][0];
                rv[(2 * p) * 2 + 1]     += lo * w3r[c][1];
                rv[(2 * p + 1) * 2 + 0] += hi * w3r[c][0];
                rv[(2 * p + 1) * 2 + 1] += hi * w3r[c][1];
            }
        }

        // ---- folding butterfly reduction: lane l ends with sum for j = l & 15 ----
#pragma unroll
        for (int j = 0; j < 16; j++) rv[j] += __shfl_xor_sync(0xffffffffu, rv[j], 16);
#pragma unroll
        for (int off = 8; off >= 1; off >>= 1) {
#pragma unroll
            for (int j = 0; j < off; j++) {
                float a = rv[j], b = rv[j + off];
                float mine  = (l & off) ? b : a;
                float other = (l & off) ? a : b;
                float recv  = __shfl_xor_sync(0xffffffffu, other, off);
                rv[j] = mine + recv;
            }
        }
        float myval = rv[0] + b3_own;  // valid for lanes l<16 as (myS, myD)

        // ---- cross-group exchange (double-buffered, one barrier per step) ----
        int bufo = (i & 1) * 256;
        if (l < 16) uf[bufo + m * 128 + (wg * 8 + myS) * 2 + myD] = myval;
        __syncthreads();

        float dt = g_dts[i], cf = g_coef[i];
        if (l < 16) {
            float ov = uf[bufo + (1 - m) * 128 + (wg * 8 + myS) * 2 + myD];
            long long gs = sbase + myS;
            long long io = (long long)i * N_SAMP;
            float xi = noise[(io + gs) * 2 + myD];
            z_own = z_own + (myval + ov) * dt + xi * cf;
            if (m == 0) out[US_OFF + (io + gs) * 2 + myD] = myval;  // u from diffusion warps
            else        out[(long long)(i + 1) * N_SAMP * 2 + gs * 2 + myD] = z_own;  // traj
        }
#pragma unroll
        for (int s = 0; s < 8; s++) {
            zz[s][0] = __shfl_sync(0xffffffffu, z_own, 2 * s);
            zz[s][1] = __shfl_sync(0xffffffffu, z_own, 2 * s + 1);
        }
    }
}

// ---------------------------------------------------------------------------
extern "C" void kernel_launch(void* const* d_in, const int* in_sizes, int n_in,
                              void* d_out, int out_size)
{
    const float* z0       = (const float*)d_in[0];
    const float* pctx     = (const float*)d_in[1];
    const float* cctx     = (const float*)d_in[2];
    const float* times    = (const float*)d_in[3];
    const float* noise    = (const float*)d_in[4];
    const float* freqs    = (const float*)d_in[5];
    const float* dW1      = (const float*)d_in[6];
    const float* db1      = (const float*)d_in[7];
    const float* dW2      = (const float*)d_in[8];
    const float* db2      = (const float*)d_in[9];
    const float* dW3      = (const float*)d_in[10];
    const float* db3      = (const float*)d_in[11];
    const float* cW1      = (const float*)d_in[12];
    const float* cb1      = (const float*)d_in[13];
    const float* cW2      = (const float*)d_in[14];
    const float* cb2      = (const float*)d_in[15];
    const float* cW3      = (const float*)d_in[16];
    const float* cb3      = (const float*)d_in[17];
    const float* log_diff = (const float*)d_in[18];
    float* out = (float*)d_out;

    const int smemB = (SPB * HID * 2 + HID * HID * 2) * 4  // base + W2
                    + NWARPS * 256 * 8                     // a1buf
                    + 2 * 2 * SPB * ZD * 4;                // uf exchange
    cudaFuncSetAttribute(sde_kernel, cudaFuncAttributeMaxDynamicSharedMemorySize, smemB);

    prep_kernel<<<1, 128>>>(times, freqs, dW1, db1, cW1, cb1, log_diff, out);
    sde_kernel<<<N_SAMP / SPB, 512, smemB>>>(z0, pctx, cctx, noise,
                                             dW1, dW2, db2, dW3, db3,
                                             cW1, cW2, cb2, cW3, cb3, out);
}

// round 4
// speedup vs baseline: 1.2538x; 1.2538x over previous
#include <cuda_runtime.h>
#include <cuda_bf16.h>
#include <cstdint>

#define N_SAMP   262144
#define ZD       2
#define CTX      128
#define HID      128
#define TEMB     32
#define NSTEPS   50
#define SPB      64      // samples per block
#define NWARPS   16      // 8 diffusion-MLP warps + 8 cnf-MLP warps

// output layout: traj [51,N,2] | us [50,N,2] | times [51]
#define US_OFF    ((long long)(NSTEPS+1) * N_SAMP * ZD)
#define TAIL_OFF  (US_OFF + (long long)NSTEPS * N_SAMP * ZD)

// per-step precomputed constants
__device__ float g_twd[NSTEPS * HID];
__device__ float g_twc[NSTEPS * HID];
__device__ float g_dts[NSTEPS];
__device__ float g_coef[NSTEPS];

typedef unsigned long long u64;

// fast silu: x*sigmoid(x) = 0.5x + 0.5x*tanh(0.5x)  (1 MUFU.TANH)
__device__ __forceinline__ float fsilu(float x) {
    float h = 0.5f * x;
    float t;
    asm("tanh.approx.f32 %0, %1;" : "=f"(t) : "f"(h));
    return fmaf(h, t, h);
}
__device__ __forceinline__ u64 f2pack(float a, float b) {
    u64 r; asm("mov.b64 %0, {%1, %2};" : "=l"(r) : "f"(a), "f"(b)); return r;
}
__device__ __forceinline__ u64 fdup(float a) {
    u64 r; asm("mov.b64 %0, {%1, %1};" : "=l"(r) : "f"(a)); return r;
}
__device__ __forceinline__ void f2unpack(u64 v, float& a, float& b) {
    asm("mov.b64 {%0, %1}, %2;" : "=f"(a), "=f"(b) : "l"(v));
}
__device__ __forceinline__ u64 ffma2(u64 a, u64 b, u64 c) {
    u64 d; asm("fma.rn.f32x2 %0, %1, %2, %3;" : "=l"(d) : "l"(a), "l"(b), "l"(c)); return d;
}
__device__ __forceinline__ void lds_v2u64(uint32_t addr, u64& x, u64& y) {
    asm volatile("ld.shared.v2.u64 {%0, %1}, [%2];" : "=l"(x), "=l"(y) : "r"(addr));
}

// ---------------------------------------------------------------------------
// Kernel A: per-step constants (temb @ W1_temb + b1, dt, diffusion coef) + times tail
// ---------------------------------------------------------------------------
__global__ void prep_kernel(const float* __restrict__ times,
                            const float* __restrict__ freqs,
                            const float* __restrict__ dW1, const float* __restrict__ db1,
                            const float* __restrict__ cW1, const float* __restrict__ cb1,
                            const float* __restrict__ log_diff,
                            float* __restrict__ out)
{
    __shared__ float temb[TEMB];
    int tid = threadIdx.x;  // 128 threads
    if (tid < NSTEPS + 1) out[TAIL_OFF + tid] = times[tid];
    float gb = log1pf(__expf(log_diff[0]));  // softplus
    for (int i = 0; i < NSTEPS; i++) {
        float t = times[i];
        __syncthreads();
        if (tid < TEMB / 2) {
            float a = 6.2831853071795864f * t * freqs[tid];
            temb[tid]            = sinf(a);
            temb[tid + TEMB / 2] = cosf(a);
        }
        __syncthreads();
        float ad = db1[tid], ac = cb1[tid];
#pragma unroll 8
        for (int m = 0; m < TEMB; m++) {
            float tv = temb[m];
            ad += tv * dW1[(ZD + CTX + m) * HID + tid];
            ac += tv * cW1[(ZD + CTX + m) * HID + tid];
        }
        g_twd[i * HID + tid] = ad;
        g_twc[i * HID + tid] = ac;
        if (tid == 0) {
            float dt = times[i + 1] - t;
            g_dts[i]  = dt;
            g_coef[i] = gb * (1.0f - t) * sqrtf(fmaxf(dt, 1e-12f));
        }
    }
}

// ---------------------------------------------------------------------------
// base = ctx @ W1[2:130] for one warp's 8 samples
// ---------------------------------------------------------------------------
__device__ __forceinline__ void compute_base(float* __restrict__ dst,
                                             const float* __restrict__ tmp,
                                             const float* __restrict__ W1,
                                             int wg, int l)
{
    float acc[8][4];
#pragma unroll
    for (int s8 = 0; s8 < 8; s8++)
#pragma unroll
        for (int c = 0; c < 4; c++) acc[s8][c] = 0.f;
#pragma unroll 2
    for (int r = 0; r < CTX; r++) {
        float w1v[4];
#pragma unroll
        for (int c = 0; c < 4; c++) w1v[c] = W1[(ZD + r) * HID + l + 32 * c];
#pragma unroll
        for (int s8 = 0; s8 < 8; s8++) {
            float a = tmp[(wg * 8 + s8) * HID + r];
#pragma unroll
            for (int c = 0; c < 4; c++) acc[s8][c] += a * w1v[c];
        }
    }
#pragma unroll
    for (int s8 = 0; s8 < 8; s8++)
#pragma unroll
        for (int c = 0; c < 4; c++)
            dst[(wg * 8 + s8) * HID + l + 32 * c] = acc[s8][c];
}

// ---------------------------------------------------------------------------
// Kernel B: persistent 50-step SDE. 512 threads / CTA, 64 samples.
// Warps 0-7: diffusion MLP (u), warps 8-15: cnf MLP (f). 8 samples per warp.
// W2 stored repacked: W2i[(k*32 + lane)*4 + c] = W2[k][lane + 32c]  -> LDS.128.
// SMEM: baseD(32K) baseC(32K) W2i_d(64K) W2i_c(64K) a1buf(32K) uf(2K) = 231424B.
// ---------------------------------------------------------------------------
__global__ void __launch_bounds__(512, 1)
sde_kernel(const float* __restrict__ z0,
           const float* __restrict__ pctx, const float* __restrict__ cctx,
           const float* __restrict__ noise,
           const float* __restrict__ dW1, const float* __restrict__ dW2,
           const float* __restrict__ db2, const float* __restrict__ dW3,
           const float* __restrict__ db3,
           const float* __restrict__ cW1, const float* __restrict__ cW2,
           const float* __restrict__ cb2, const float* __restrict__ cW3,
           const float* __restrict__ cb3,
           float* __restrict__ out)
{
    extern __shared__ float sm[];
    float* baseD = sm;                       // 64*128
    float* baseC = baseD + SPB * HID;        // 64*128
    float* sW2d  = baseC + SPB * HID;        // 128*128 (repacked)
    float* sW2c  = sW2d + HID * HID;         // 128*128 (repacked)
    u64*   a1buf = (u64*)(sW2c + HID * HID); // 16 warps * 256 u64
    float* uf    = (float*)(a1buf + NWARPS * 256); // 2 bufs * 2 mlp * 64 * 2

    int tid = threadIdx.x;
    int w = tid >> 5, l = tid & 31;
    int m  = w >> 3;      // 0 = diffusion MLP (u), 1 = cnf MLP (f)
    int wg = w & 7;       // sample group
    int blockBase = blockIdx.x * SPB;
    int sbase = blockBase + wg * 8;
    int myS = l >> 1, myD = l & 1;

    const float* W1 = m ? cW1 : dW1;

    // ---- phase 1: stage ctx tiles into W2 areas, compute base, then load W2 ----
    for (int idx = tid; idx < SPB * HID; idx += 512) {
        sW2d[idx] = pctx[(long long)blockBase * HID + idx];
        sW2c[idx] = cctx[(long long)blockBase * HID + idx];
    }
    __syncthreads();
    {
        const float* tmp = m ? sW2c : sW2d;
        float* dstBase   = m ? baseC : baseD;
        compute_base(dstBase, tmp, W1, wg, l);
    }
    __syncthreads();
    // repacked W2 load: W2i[(k*32 + j%32)*4 + j/32] = W2[k*128 + j]
    for (int idx = tid; idx < HID * HID; idx += 512) {
        int k = idx >> 7, j = idx & 127;
        int dst = ((k << 5) + (j & 31)) * 4 + (j >> 5);
        sW2d[dst] = dW2[idx];
        sW2c[dst] = cW2[idx];
    }
    __syncthreads();

    // ---- per-lane constant weights in registers (single MLP) ----
    const float* W2s   = m ? sW2c : sW2d;
    const float* W3    = m ? cW3  : dW3;
    const float* b2    = m ? cb2  : db2;
    const float* b3    = m ? cb3  : db3;
    const float* twAll = m ? g_twc : g_twd;
    const float* bsw   = (m ? baseC : baseD) + wg * 8 * HID;
    const float4* W2v  = (const float4*)W2s;

    float wzr[2][4], w3r[4][2], b2r[4];
#pragma unroll
    for (int c = 0; c < 4; c++) {
        int j = l + 32 * c;
        wzr[0][c] = W1[0 * HID + j];
        wzr[1][c] = W1[1 * HID + j];
        w3r[c][0] = W3[j * ZD + 0];
        w3r[c][1] = W3[j * ZD + 1];
        b2r[c]    = b2[j];
    }
    float b3_own = b3[myD];

    // ---- init z (owner lanes l<16 hold (s = l>>1, d = l&1)); cnf warps write traj[0] ----
    float z_own = 0.f;
    if (l < 16) {
        long long gs = sbase + myS;
        z_own = z0[gs * ZD + myD];
        if (m) out[gs * ZD + myD] = z_own;  // traj[0]
    }
    float zz[8][2];
#pragma unroll
    for (int s = 0; s < 8; s++) {
        zz[s][0] = __shfl_sync(0xffffffffu, z_own, 2 * s);
        zz[s][1] = __shfl_sync(0xffffffffu, z_own, 2 * s + 1);
    }

    uint32_t myA = (uint32_t)__cvta_generic_to_shared(a1buf + w * 256);

    // ---- 50-step loop ----
    for (int i = 0; i < NSTEPS; i++) {
        // prefetch step constants + noise early (hide latency behind the MLP)
        float twr[4];
#pragma unroll
        for (int c = 0; c < 4; c++) twr[c] = twAll[i * HID + l + 32 * c];
        float dt = g_dts[i], cf = g_coef[i];
        long long gs = sbase + myS;
        long long io = (long long)i * N_SAMP;
        float xi = 0.f;
        if (l < 16) xi = noise[(io + gs) * 2 + myD];

        u64 acc[4][4];
#pragma unroll
        for (int p = 0; p < 4; p++)
#pragma unroll
            for (int c = 0; c < 4; c++) acc[p][c] = 0ull;

#pragma unroll
        for (int ch = 0; ch < 2; ch++) {
            __syncwarp();
            // layer 1 (rank-2 update) + silu -> packed sample-pairs in a1buf
#pragma unroll
            for (int p = 0; p < 4; p++) {
#pragma unroll
                for (int t = 0; t < 2; t++) {
                    int kk = l + 32 * t;
                    int k  = ch * 64 + kk;
                    int c  = ch * 2 + t;
                    float twv = twr[c];
                    int s0 = 2 * p;
                    float h0 = bsw[s0 * HID + k] + twv
                             + zz[2 * p][0]     * wzr[0][c] + zz[2 * p][1]     * wzr[1][c];
                    float h1 = bsw[(s0 + 1) * HID + k] + twv
                             + zz[2 * p + 1][0] * wzr[0][c] + zz[2 * p + 1][1] * wzr[1][c];
                    a1buf[w * 256 + p * 64 + kk] = f2pack(fsilu(h0), fsilu(h1));
                }
            }
            __syncwarp();
            // layer 2: packed fp32x2 GEMM, k unrolled by 2.
            // A: 4x LDS.128 broadcast (2 k-values per pair); B: 2x LDS.128 (repacked W2)
#pragma unroll 8
            for (int kk = 0; kk < 64; kk += 2) {
                int k = ch * 64 + kk;
                u64 A0[4], A1[4];
#pragma unroll
                for (int p = 0; p < 4; p++)
                    lds_v2u64(myA + (p * 64 + kk) * 8, A0[p], A1[p]);
                float4 bv0 = W2v[(k)     * 32 + l];
                float4 bv1 = W2v[(k + 1) * 32 + l];
                u64 B0[4], B1[4];
                B0[0] = fdup(bv0.x); B0[1] = fdup(bv0.y); B0[2] = fdup(bv0.z); B0[3] = fdup(bv0.w);
                B1[0] = fdup(bv1.x); B1[1] = fdup(bv1.y); B1[2] = fdup(bv1.z); B1[3] = fdup(bv1.w);
#pragma unroll
                for (int p = 0; p < 4; p++)
#pragma unroll
                    for (int c = 0; c < 4; c++) {
                        acc[p][c] = ffma2(A0[p], B0[c], acc[p][c]);
                        acc[p][c] = ffma2(A1[p], B1[c], acc[p][c]);
                    }
            }
        }

        // epilogue: silu(h2 + b2), layer-3 partials
        float rv[16];
#pragma unroll
        for (int j = 0; j < 16; j++) rv[j] = 0.f;
#pragma unroll
        for (int p = 0; p < 4; p++) {
#pragma unroll
            for (int c = 0; c < 4; c++) {
                float lo, hi;
                f2unpack(acc[p][c], lo, hi);
                lo = fsilu(lo + b2r[c]);
                hi = fsilu(hi + b2r[c]);
                rv[(2 * p) * 2 + 0]     += lo * w3r[c][0];
                rv[(2 * p) * 2 + 1]     += lo * w3r[c][1];
                rv[(2 * p + 1) * 2 + 0] += hi * w3r[c][0];
                rv[(2 * p + 1) * 2 + 1] += hi * w3r[c][1];
            }
        }

        // ---- folding butterfly reduction: lane l ends with sum for j = l & 15 ----
#pragma unroll
        for (int j = 0; j < 16; j++) rv[j] += __shfl_xor_sync(0xffffffffu, rv[j], 16);
#pragma unroll
        for (int off = 8; off >= 1; off >>= 1) {
#pragma unroll
            for (int j = 0; j < off; j++) {
                float a = rv[j], b = rv[j + off];
                float mine  = (l & off) ? b : a;
                float other = (l & off) ? a : b;
                float recv  = __shfl_xor_sync(0xffffffffu, other, off);
                rv[j] = mine + recv;
            }
        }
        float myval = rv[0] + b3_own;  // valid for lanes l<16 as (myS, myD)

        // ---- cross-group exchange (double-buffered, one barrier per step) ----
        int bufo = (i & 1) * 256;
        if (l < 16) uf[bufo + m * 128 + (wg * 8 + myS) * 2 + myD] = myval;
        __syncthreads();

        if (l < 16) {
            float ov = uf[bufo + (1 - m) * 128 + (wg * 8 + myS) * 2 + myD];
            z_own = z_own + (myval + ov) * dt + xi * cf;
            if (m == 0) out[US_OFF + (io + gs) * 2 + myD] = myval;  // u from diffusion warps
            else        out[(long long)(i + 1) * N_SAMP * 2 + gs * 2 + myD] = z_own;  // traj
        }
#pragma unroll
        for (int s = 0; s < 8; s++) {
            zz[s][0] = __shfl_sync(0xffffffffu, z_own, 2 * s);
            zz[s][1] = __shfl_sync(0xffffffffu, z_own, 2 * s + 1);
        }
    }
}

// ---------------------------------------------------------------------------
extern "C" void kernel_launch(void* const* d_in, const int* in_sizes, int n_in,
                              void* d_out, int out_size)
{
    const float* z0       = (const float*)d_in[0];
    const float* pctx     = (const float*)d_in[1];
    const float* cctx     = (const float*)d_in[2];
    const float* times    = (const float*)d_in[3];
    const float* noise    = (const float*)d_in[4];
    const float* freqs    = (const float*)d_in[5];
    const float* dW1      = (const float*)d_in[6];
    const float* db1      = (const float*)d_in[7];
    const float* dW2      = (const float*)d_in[8];
    const float* db2      = (const float*)d_in[9];
    const float* dW3      = (const float*)d_in[10];
    const float* db3      = (const float*)d_in[11];
    const float* cW1      = (const float*)d_in[12];
    const float* cb1      = (const float*)d_in[13];
    const float* cW2      = (const float*)d_in[14];
    const float* cb2      = (const float*)d_in[15];
    const float* cW3      = (const float*)d_in[16];
    const float* cb3      = (const float*)d_in[17];
    const float* log_diff = (const float*)d_in[18];
    float* out = (float*)d_out;

    const int smemB = (SPB * HID * 2 + HID * HID * 2) * 4  // base + W2
                    + NWARPS * 256 * 8                     // a1buf
                    + 2 * 2 * SPB * ZD * 4;                // uf exchange
    cudaFuncSetAttribute(sde_kernel, cudaFuncAttributeMaxDynamicSharedMemorySize, smemB);

    prep_kernel<<<1, 128>>>(times, freqs, dW1, db1, cW1, cb1, log_diff, out);
    sde_kernel<<<N_SAMP / SPB, 512, smemB>>>(z0, pctx, cctx, noise,
                                             dW1, dW2, db2, dW3, db3,
                                             cW1, cW2, cb2, cW3, cb3, out);
}

// round 5
// speedup vs baseline: 1.5411x; 1.2291x over previous
#include <cuda_runtime.h>
#include <cuda_bf16.h>
#include <cstdint>

#define N_SAMP   262144
#define ZD       2
#define CTX      128
#define HID      128
#define TEMB     32
#define NSTEPS   50
#define SPB      64      // samples per block
#define NWARPS   16      // 8 diffusion-MLP warps + 8 cnf-MLP warps

// output layout: traj [51,N,2] | us [50,N,2] | times [51]
#define US_OFF    ((long long)(NSTEPS+1) * N_SAMP * ZD)
#define TAIL_OFF  (US_OFF + (long long)NSTEPS * N_SAMP * ZD)

// per-step constants, tw permuted into per-lane fragment order:
// idx = i*128 + kt*16 + t*4 + comp,  comp = reg*2 + half  (k = kt*16 + 2t + reg*8 + half)
__device__ float g_twd[NSTEPS * HID];
__device__ float g_twc[NSTEPS * HID];
__device__ float g_dts[NSTEPS];
__device__ float g_coef[NSTEPS];

// fast silu: x*sigmoid(x) = 0.5x + 0.5x*tanh(0.5x)  (1 MUFU.TANH)
__device__ __forceinline__ float fsilu(float x) {
    float h = 0.5f * x;
    float t;
    asm("tanh.approx.f32 %0, %1;" : "=f"(t) : "f"(h));
    return fmaf(h, t, h);
}
// pack: lower half = lo_k (even k), upper half = hi_k (odd k)
__device__ __forceinline__ uint32_t cvt2bf(float odd_k, float even_k) {
    uint32_t r; asm("cvt.rn.bf16x2.f32 %0, %1, %2;" : "=r"(r) : "f"(odd_k), "f"(even_k)); return r;
}
__device__ __forceinline__ void mma16816(float* d, uint32_t a0, uint32_t a2,
                                         uint32_t b0, uint32_t b1) {
    uint32_t zr = 0;
    asm volatile("mma.sync.aligned.m16n8k16.row.col.f32.bf16.bf16.f32 "
                 "{%0,%1,%2,%3}, {%4,%5,%6,%7}, {%8,%9}, {%0,%1,%2,%3};"
                 : "+f"(d[0]), "+f"(d[1]), "+f"(d[2]), "+f"(d[3])
                 : "r"(a0), "r"(zr), "r"(a2), "r"(zr), "r"(b0), "r"(b1));
}

// fragment position helpers (k within 128): kt = k>>4, kr = k&15
// t = (kr&7)>>1, reg = (kr>>3)&1, half = kr&1, comp = reg*2 + half
__host__ __device__ __forceinline__ int frag_comp(int kr) { return (((kr >> 3) & 1) << 1) | (kr & 1); }

// ---------------------------------------------------------------------------
// Kernel A: per-step constants (temb @ W1_temb + b1 in permuted layout) + times tail
// ---------------------------------------------------------------------------
__global__ void prep_kernel(const float* __restrict__ times,
                            const float* __restrict__ freqs,
                            const float* __restrict__ dW1, const float* __restrict__ db1,
                            const float* __restrict__ cW1, const float* __restrict__ cb1,
                            const float* __restrict__ log_diff,
                            float* __restrict__ out)
{
    __shared__ float temb[TEMB];
    int tid = threadIdx.x;  // 128 threads, tid = k
    if (tid < NSTEPS + 1) out[TAIL_OFF + tid] = times[tid];
    int kt = tid >> 4, kr = tid & 15;
    int pidx = kt * 16 + ((kr & 7) >> 1) * 4 + frag_comp(kr);  // permuted position
    float gb = log1pf(__expf(log_diff[0]));  // softplus
    for (int i = 0; i < NSTEPS; i++) {
        float t = times[i];
        __syncthreads();
        if (tid < TEMB / 2) {
            float a = 6.2831853071795864f * t * freqs[tid];
            temb[tid]            = sinf(a);
            temb[tid + TEMB / 2] = cosf(a);
        }
        __syncthreads();
        float ad = db1[tid], ac = cb1[tid];
#pragma unroll 8
        for (int mm = 0; mm < TEMB; mm++) {
            float tv = temb[mm];
            ad += tv * dW1[(ZD + CTX + mm) * HID + tid];
            ac += tv * cW1[(ZD + CTX + mm) * HID + tid];
        }
        g_twd[i * HID + pidx] = ad;
        g_twc[i * HID + pidx] = ac;
        if (tid == 0) {
            float dt = times[i + 1] - t;
            g_dts[i]  = dt;
            g_coef[i] = gb * (1.0f - t) * sqrtf(fmaxf(dt, 1e-12f));
        }
    }
}

// ---------------------------------------------------------------------------
// base = ctx @ W1[2:130] for one warp's 8 samples (old [s][k] layout)
// ---------------------------------------------------------------------------
__device__ __forceinline__ void compute_base(float* __restrict__ dst,
                                             const float* __restrict__ tmp,
                                             const float* __restrict__ W1,
                                             int wg, int l)
{
    float acc[8][4];
#pragma unroll
    for (int s8 = 0; s8 < 8; s8++)
#pragma unroll
        for (int c = 0; c < 4; c++) acc[s8][c] = 0.f;
#pragma unroll 2
    for (int r = 0; r < CTX; r++) {
        float w1v[4];
#pragma unroll
        for (int c = 0; c < 4; c++) w1v[c] = W1[(ZD + r) * HID + l + 32 * c];
#pragma unroll
        for (int s8 = 0; s8 < 8; s8++) {
            float a = tmp[(wg * 8 + s8) * HID + r];
#pragma unroll
            for (int c = 0; c < 4; c++) acc[s8][c] += a * w1v[c];
        }
    }
#pragma unroll
    for (int s8 = 0; s8 < 8; s8++)
#pragma unroll
        for (int c = 0; c < 4; c++)
            dst[(wg * 8 + s8) * HID + l + 32 * c] = acc[s8][c];
}

// ---------------------------------------------------------------------------
// Kernel B: persistent 50-step SDE, tensor-core layer-2 (split-bf16 mma).
// 512 threads: warps 0-7 diffusion MLP, warps 8-15 cnf MLP, 8 samples/warp.
// SMEM: BfD(64K) BfC(64K) baseRD(32K) baseRC(32K) + small tables + uf ≈ 199KB.
// ---------------------------------------------------------------------------
__global__ void __launch_bounds__(512, 1)
sde_kernel(const float* __restrict__ z0,
           const float* __restrict__ pctx, const float* __restrict__ cctx,
           const float* __restrict__ noise,
           const float* __restrict__ dW1, const float* __restrict__ dW2,
           const float* __restrict__ db2, const float* __restrict__ dW3,
           const float* __restrict__ db3,
           const float* __restrict__ cW1, const float* __restrict__ cW2,
           const float* __restrict__ cb2, const float* __restrict__ cW3,
           const float* __restrict__ cb3,
           float* __restrict__ out)
{
    extern __shared__ float sm[];
    uint4* BfD    = (uint4*)sm;              // 8kt*16nt*32lane uint4 = 64KB
    uint4* BfC    = BfD + 4096;              // 64KB
    float* baseRD = (float*)(BfC + 4096);    // 8 wg * 1024 floats = 32KB
    float* baseRC = baseRD + 8192;           // 32KB
    float* wzRs   = baseRC + 8192;           // [mlp][row][kt][t] float4 = 512 f
    float* b2Rs   = wzRs + 512;              // [mlp][ntg][t] float2 = 256 f
    float* W3Rs   = b2Rs + 256;              // [mlp][ntg][t] float4 = 512 f
    float2* uf2   = (float2*)(W3Rs + 512);   // [2 buf][2 mlp][64] float2

    int tid = threadIdx.x;
    int w = tid >> 5, l = tid & 31;
    int m  = w >> 3;       // 0 = diffusion (u), 1 = cnf (f)
    int wg = w & 7;        // sample group of 8
    int t3 = l & 3;        // quad thread
    int g  = l >> 2;       // sample within group (row in mma)
    int blockBase = blockIdx.x * SPB;
    int gs = blockBase + wg * 8 + g;   // my sample

    const float* W1g = m ? cW1 : dW1;
    const float* W2g = m ? cW2 : dW2;

    // ================= phase 1 =================
    // 1) stage ctx tiles into the (not yet used) Bfrag regions
    {
        float* tD = (float*)BfD;
        float* tC = (float*)BfC;
        for (int idx = tid; idx < SPB * HID; idx += 512) {
            tD[idx] = pctx[(long long)blockBase * HID + idx];
            tC[idx] = cctx[(long long)blockBase * HID + idx];
        }
    }
    __syncthreads();
    // 2) base in old [s][k] layout
    compute_base(m ? baseRC : baseRD, (float*)(m ? (void*)BfC : (void*)BfD), W1g, wg, l);
    __syncthreads();
    // 3) in-place permute base -> fragment order: [wg][kt][lane(g*4+t)][comp]
    {
        float tmpD[16], tmpC[16];
#pragma unroll
        for (int q = 0; q < 16; q++) {
            tmpD[q] = baseRD[tid * 16 + q];
            tmpC[q] = baseRC[tid * 16 + q];
        }
        __syncthreads();
#pragma unroll
        for (int q = 0; q < 16; q++) {
            int idx = tid * 16 + q;
            int s = idx >> 7, k = idx & 127;
            int swg = s >> 3, sg = s & 7;
            int kt = k >> 4, kr = k & 15;
            int lane = sg * 4 + ((kr & 7) >> 1);
            int ni = swg * 1024 + (kt * 32 + lane) * 4 + frag_comp(kr);
            baseRD[ni] = tmpD[q];
            baseRC[ni] = tmpC[q];
        }
    }
    __syncthreads();
    // 4) W2 -> bf16 hi/lo in B-fragment layout; plus small tables
    {
        unsigned short* bD16 = (unsigned short*)BfD;
        unsigned short* bC16 = (unsigned short*)BfC;
        for (int e = tid; e < HID * HID; e += 512) {
            int k = e >> 7, j = e & 127;
            int kt = k >> 4, kr = k & 15;
            int reg = (kr >> 3) & 1, half = kr & 1;
            int lane = (j & 7) * 4 + ((kr & 7) >> 1);
            int ntg = j >> 3;
            int slot = (((kt * 16 + ntg) * 32 + lane) * 4);
            {
                float wv = dW2[e];
                __nv_bfloat16 hb = __float2bfloat16(wv);
                __nv_bfloat16 lb = __float2bfloat16(wv - __bfloat162float(hb));
                bD16[(slot + reg) * 2 + half]     = __bfloat16_as_ushort(hb);
                bD16[(slot + 2 + reg) * 2 + half] = __bfloat16_as_ushort(lb);
            }
            {
                float wv = cW2[e];
                __nv_bfloat16 hb = __float2bfloat16(wv);
                __nv_bfloat16 lb = __float2bfloat16(wv - __bfloat162float(hb));
                bC16[(slot + reg) * 2 + half]     = __bfloat16_as_ushort(hb);
                bC16[(slot + 2 + reg) * 2 + half] = __bfloat16_as_ushort(lb);
            }
        }
        // wzR: [mlp][row][kt][t][comp]
        for (int idx = tid; idx < 2 * 2 * HID; idx += 512) {
            int mlp = idx >> 8, row = (idx >> 7) & 1, k = idx & 127;
            int kt = k >> 4, kr = k & 15;
            float v = (mlp ? cW1 : dW1)[row * HID + k];
            wzRs[((mlp * 2 + row) * 8 + kt) * 16 + ((kr & 7) >> 1) * 4 + frag_comp(kr)] = v;
        }
        // b2R: [mlp][ntg][t][half]   (j = ntg*8 + 2t + half)
        for (int idx = tid; idx < 2 * HID; idx += 512) {
            int mlp = idx >> 7, j = idx & 127;
            float v = (mlp ? cb2 : db2)[j];
            b2Rs[(mlp * 16 + (j >> 3)) * 8 + ((j & 7) >> 1) * 2 + (j & 1)] = v;
        }
        // W3R: [mlp][ntg][t][(j&1)*2 + d]
        for (int idx = tid; idx < 2 * HID * ZD; idx += 512) {
            int mlp = idx >> 8, j = (idx >> 1) & 127, d = idx & 1;
            float v = (mlp ? cW3 : dW3)[j * ZD + d];
            W3Rs[(mlp * 16 + (j >> 3)) * 16 + ((j & 7) >> 1) * 4 + (j & 1) * 2 + d] = v;
        }
    }
    __syncthreads();

    // ================= per-warp constant pointers / regs =================
    const uint4*  Bf    = m ? BfC : BfD;
    const float4* bR4   = (const float4*)((m ? baseRC : baseRD) + wg * 1024);
    const float4* twR4  = (const float4*)(m ? g_twc : g_twd);
    const float4* wz04  = (const float4*)wzRs + (m * 2 + 0) * 32;
    const float4* wz14  = (const float4*)wzRs + (m * 2 + 1) * 32;
    const float2* b2R2  = (const float2*)b2Rs + m * 64;
    const float4* W3R4  = (const float4*)W3Rs + m * 64;
    const float2* noise2 = (const float2*)noise;
    float2* outTraj = (float2*)out;
    float2* outUS   = (float2*)(out + US_OFF);

    float b3_0, b3_1;
    { const float* b3 = m ? cb3 : db3; b3_0 = b3[0]; b3_1 = b3[1]; }

    // init z (all lanes of quad hold sample gs's z)
    float2 zi = __ldg(&((const float2*)z0)[gs]);
    float z0v = zi.x, z1v = zi.y;
    if (m == 1 && t3 == 0) outTraj[gs] = zi;  // traj[0]

    // ================= 50-step loop =================
    for (int i = 0; i < NSTEPS; i++) {
        float dt = g_dts[i], cf = g_coef[i];
        long long io = (long long)i * N_SAMP;
        float2 xi = __ldg(&noise2[io + gs]);

        // ---- layer 1 -> A fragments (hi/lo bf16), fully in registers ----
        uint32_t Ahi[8][2], Alo[8][2];
#pragma unroll
        for (int kt = 0; kt < 8; kt++) {
            float4 bs = bR4[kt * 32 + l];
            float4 tw = __ldg(&twR4[i * 32 + kt * 4 + t3]);
            float4 w0 = wz04[kt * 4 + t3];
            float4 w1 = wz14[kt * 4 + t3];
            float hx = fsilu(bs.x + tw.x + z0v * w0.x + z1v * w1.x);
            float hy = fsilu(bs.y + tw.y + z0v * w0.y + z1v * w1.y);
            float hz = fsilu(bs.z + tw.z + z0v * w0.z + z1v * w1.z);
            float hw = fsilu(bs.w + tw.w + z0v * w0.w + z1v * w1.w);
            uint32_t h01 = cvt2bf(hy, hx);
            uint32_t h23 = cvt2bf(hw, hz);
            float l0 = hx - __uint_as_float(h01 << 16);
            float l1 = hy - __uint_as_float(h01 & 0xffff0000u);
            float l2 = hz - __uint_as_float(h23 << 16);
            float l3 = hw - __uint_as_float(h23 & 0xffff0000u);
            Ahi[kt][0] = h01; Ahi[kt][1] = h23;
            Alo[kt][0] = cvt2bf(l1, l0);
            Alo[kt][1] = cvt2bf(l3, l2);
        }

        // ---- layer 2 (tensor) + layer 3 partials ----
        float acc0 = 0.f, acc1 = 0.f;
#pragma unroll
        for (int pass = 0; pass < 2; pass++) {
            float d[8][4];
#pragma unroll
            for (int nt = 0; nt < 8; nt++)
#pragma unroll
                for (int c = 0; c < 4; c++) d[nt][c] = 0.f;
#pragma unroll
            for (int kt = 0; kt < 8; kt++) {
#pragma unroll
                for (int ntc = 0; ntc < 8; ntc += 4) {
                    uint4 Bv[4];
#pragma unroll
                    for (int q = 0; q < 4; q++)
                        Bv[q] = Bf[(kt * 16 + pass * 8 + ntc + q) * 32 + l];
#pragma unroll
                    for (int q = 0; q < 4; q++) mma16816(d[ntc + q], Ahi[kt][0], Ahi[kt][1], Bv[q].x, Bv[q].y);
#pragma unroll
                    for (int q = 0; q < 4; q++) mma16816(d[ntc + q], Alo[kt][0], Alo[kt][1], Bv[q].x, Bv[q].y);
#pragma unroll
                    for (int q = 0; q < 4; q++) mma16816(d[ntc + q], Ahi[kt][0], Ahi[kt][1], Bv[q].z, Bv[q].w);
                }
            }
            // epilogue for this pass
#pragma unroll
            for (int nt = 0; nt < 8; nt++) {
                int ntg = pass * 8 + nt;
                float2 b2v = b2R2[ntg * 4 + t3];
                float4 w3v = W3R4[ntg * 4 + t3];
                float x0 = fsilu(d[nt][0] + b2v.x);
                float x1 = fsilu(d[nt][1] + b2v.y);
                acc0 += x0 * w3v.x + x1 * w3v.z;
                acc1 += x0 * w3v.y + x1 * w3v.w;
            }
        }

        // ---- quad reduction (4 lanes share one sample) ----
        acc0 += __shfl_xor_sync(0xffffffffu, acc0, 1);
        acc1 += __shfl_xor_sync(0xffffffffu, acc1, 1);
        acc0 += __shfl_xor_sync(0xffffffffu, acc0, 2);
        acc1 += __shfl_xor_sync(0xffffffffu, acc1, 2);
        float v0 = acc0 + b3_0;
        float v1 = acc1 + b3_1;

        // ---- cross-MLP exchange (double buffered, one barrier per step) ----
        int bufo = (i & 1) * 128;
        if (t3 == 0) uf2[bufo + m * 64 + wg * 8 + g] = make_float2(v0, v1);
        __syncthreads();
        float2 ov = uf2[bufo + (1 - m) * 64 + wg * 8 + g];

        z0v += (v0 + ov.x) * dt + xi.x * cf;
        z1v += (v1 + ov.y) * dt + xi.y * cf;
        if (t3 == 0) {
            if (m == 0) outUS[io + gs] = make_float2(v0, v1);
            else        outTraj[(long long)(i + 1) * N_SAMP + gs] = make_float2(z0v, z1v);
        }
    }
}

// ---------------------------------------------------------------------------
extern "C" void kernel_launch(void* const* d_in, const int* in_sizes, int n_in,
                              void* d_out, int out_size)
{
    const float* z0       = (const float*)d_in[0];
    const float* pctx     = (const float*)d_in[1];
    const float* cctx     = (const float*)d_in[2];
    const float* times    = (const float*)d_in[3];
    const float* noise    = (const float*)d_in[4];
    const float* freqs    = (const float*)d_in[5];
    const float* dW1      = (const float*)d_in[6];
    const float* db1      = (const float*)d_in[7];
    const float* dW2      = (const float*)d_in[8];
    const float* db2      = (const float*)d_in[9];
    const float* dW3      = (const float*)d_in[10];
    const float* db3      = (const float*)d_in[11];
    const float* cW1      = (const float*)d_in[12];
    const float* cb1      = (const float*)d_in[13];
    const float* cW2      = (const float*)d_in[14];
    const float* cb2      = (const float*)d_in[15];
    const float* cW3      = (const float*)d_in[16];
    const float* cb3      = (const float*)d_in[17];
    const float* log_diff = (const float*)d_in[18];
    float* out = (float*)d_out;

    // Bf 2*64KB + baseR 2*32KB + wzR 2KB + b2R 1KB + W3R 2KB + uf 2KB
    const int smemB = 2 * 65536 + 2 * 32768 + 512 * 4 + 256 * 4 + 512 * 4 + 256 * 8;
    cudaFuncSetAttribute(sde_kernel, cudaFuncAttributeMaxDynamicSharedMemorySize, smemB);

    prep_kernel<<<1, 128>>>(times, freqs, dW1, db1, cW1, cb1, log_diff, out);
    sde_kernel<<<N_SAMP / SPB, 512, smemB>>>(z0, pctx, cctx, noise,
                                             dW1, dW2, db2, dW3, db3,
                                             cW1, cW2, cb2, cW3, cb3, out);
}

// round 6
// speedup vs baseline: 2.3912x; 1.5516x over previous
#include <cuda_runtime.h>
#include <cuda_bf16.h>
#include <cstdint>

#define N_SAMP   262144
#define ZD       2
#define CTX      128
#define HID      128
#define TEMB     32
#define NSTEPS   50
#define SPB      64      // samples per block
#define NTHREADS 256     // 8 warps: 4 diffusion + 4 cnf, 16 samples each

// output layout: traj [51,N,2] | us [50,N,2] | times [51]
#define US_OFF    ((long long)(NSTEPS+1) * N_SAMP * ZD)
#define TAIL_OFF  (US_OFF + (long long)NSTEPS * N_SAMP * ZD)

// per-step constants, tw permuted into per-lane fragment order:
// idx = i*128 + kt*16 + t*4 + comp,  comp = reg*2 + half  (k = kt*16 + 2t + reg*8 + half)
__device__ float g_twd[NSTEPS * HID];
__device__ float g_twc[NSTEPS * HID];
__device__ float g_dts[NSTEPS];
__device__ float g_coef[NSTEPS];

// fast silu: x*sigmoid(x) = 0.5x + 0.5x*tanh(0.5x)  (1 MUFU.TANH)
__device__ __forceinline__ float fsilu(float x) {
    float h = 0.5f * x;
    float t;
    asm("tanh.approx.f32 %0, %1;" : "=f"(t) : "f"(h));
    return fmaf(h, t, h);
}
// pack: lower half = even-k val, upper half = odd-k val
__device__ __forceinline__ uint32_t cvt2bf(float odd_k, float even_k) {
    uint32_t r; asm("cvt.rn.bf16x2.f32 %0, %1, %2;" : "=r"(r) : "f"(odd_k), "f"(even_k)); return r;
}
__device__ __forceinline__ void mma16816(float* d, uint32_t a0, uint32_t a1,
                                         uint32_t a2, uint32_t a3,
                                         uint32_t b0, uint32_t b1) {
    asm volatile("mma.sync.aligned.m16n8k16.row.col.f32.bf16.bf16.f32 "
                 "{%0,%1,%2,%3}, {%4,%5,%6,%7}, {%8,%9}, {%0,%1,%2,%3};"
                 : "+f"(d[0]), "+f"(d[1]), "+f"(d[2]), "+f"(d[3])
                 : "r"(a0), "r"(a1), "r"(a2), "r"(a3), "r"(b0), "r"(b1));
}

// fragment position helpers (k within 128): kt = k>>4, kr = k&15
// t = (kr&7)>>1, reg = (kr>>3)&1, half = kr&1, comp = reg*2 + half
__host__ __device__ __forceinline__ int frag_comp(int kr) { return (((kr >> 3) & 1) << 1) | (kr & 1); }

// ---------------------------------------------------------------------------
// Kernel A: per-step constants (temb @ W1_temb + b1 in permuted layout) + times tail
// ---------------------------------------------------------------------------
__global__ void prep_kernel(const float* __restrict__ times,
                            const float* __restrict__ freqs,
                            const float* __restrict__ dW1, const float* __restrict__ db1,
                            const float* __restrict__ cW1, const float* __restrict__ cb1,
                            const float* __restrict__ log_diff,
                            float* __restrict__ out)
{
    __shared__ float temb[TEMB];
    int tid = threadIdx.x;  // 128 threads, tid = k
    if (tid < NSTEPS + 1) out[TAIL_OFF + tid] = times[tid];
    int kt = tid >> 4, kr = tid & 15;
    int pidx = kt * 16 + ((kr & 7) >> 1) * 4 + frag_comp(kr);  // permuted position
    float gb = log1pf(__expf(log_diff[0]));  // softplus
    for (int i = 0; i < NSTEPS; i++) {
        float t = times[i];
        __syncthreads();
        if (tid < TEMB / 2) {
            float a = 6.2831853071795864f * t * freqs[tid];
            temb[tid]            = sinf(a);
            temb[tid + TEMB / 2] = cosf(a);
        }
        __syncthreads();
        float ad = db1[tid], ac = cb1[tid];
#pragma unroll 8
        for (int mm = 0; mm < TEMB; mm++) {
            float tv = temb[mm];
            ad += tv * dW1[(ZD + CTX + mm) * HID + tid];
            ac += tv * cW1[(ZD + CTX + mm) * HID + tid];
        }
        g_twd[i * HID + pidx] = ad;
        g_twc[i * HID + pidx] = ac;
        if (tid == 0) {
            float dt = times[i + 1] - t;
            g_dts[i]  = dt;
            g_coef[i] = gb * (1.0f - t) * sqrtf(fmaxf(dt, 1e-12f));
        }
    }
}

// ---------------------------------------------------------------------------
// base = ctx @ W1[2:130] for one group of 8 samples (old [s][k] layout)
// ---------------------------------------------------------------------------
__device__ __forceinline__ void compute_base(float* __restrict__ dst,
                                             const float* __restrict__ tmp,
                                             const float* __restrict__ W1,
                                             int grp, int l)
{
    float acc[8][4];
#pragma unroll
    for (int s8 = 0; s8 < 8; s8++)
#pragma unroll
        for (int c = 0; c < 4; c++) acc[s8][c] = 0.f;
#pragma unroll 2
    for (int r = 0; r < CTX; r++) {
        float w1v[4];
#pragma unroll
        for (int c = 0; c < 4; c++) w1v[c] = W1[(ZD + r) * HID + l + 32 * c];
#pragma unroll
        for (int s8 = 0; s8 < 8; s8++) {
            float a = tmp[(grp * 8 + s8) * HID + r];
#pragma unroll
            for (int c = 0; c < 4; c++) acc[s8][c] += a * w1v[c];
        }
    }
#pragma unroll
    for (int s8 = 0; s8 < 8; s8++)
#pragma unroll
        for (int c = 0; c < 4; c++)
            dst[(grp * 8 + s8) * HID + l + 32 * c] = acc[s8][c];
}

// ---------------------------------------------------------------------------
// Kernel B: persistent 50-step SDE, tensor-core layer-2, 16 REAL samples/warp.
// 256 threads: warps 0-3 diffusion MLP, warps 4-7 cnf MLP, 16 samples/warp.
// SMEM: BfD(64K) BfC(64K) baseRD(32K) baseRC(32K) + tables + uf ≈ 201KB.
// ---------------------------------------------------------------------------
__global__ void __launch_bounds__(NTHREADS, 1)
sde_kernel(const float* __restrict__ z0,
           const float* __restrict__ pctx, const float* __restrict__ cctx,
           const float* __restrict__ noise,
           const float* __restrict__ dW1, const float* __restrict__ dW2,
           const float* __restrict__ db2, const float* __restrict__ dW3,
           const float* __restrict__ db3,
           const float* __restrict__ cW1, const float* __restrict__ cW2,
           const float* __restrict__ cb2, const float* __restrict__ cW3,
           const float* __restrict__ cb3,
           float* __restrict__ out)
{
    extern __shared__ float sm[];
    uint4* BfD    = (uint4*)sm;              // 8kt*16ntg*32lane uint4 = 64KB
    uint4* BfC    = BfD + 4096;              // 64KB
    float* baseRD = (float*)(BfC + 4096);    // 4 wg * 2048 floats = 32KB
    float* baseRC = baseRD + 8192;           // 32KB
    float* wzRs   = baseRC + 8192;           // [mlp][row][kt][t] float4 = 512 f
    float* b2Rs   = wzRs + 512;              // [mlp][ntg][t] float2 = 256 f
    float* W3Rs   = b2Rs + 256;              // [mlp][ntg][t] float4 = 512 f
    float2* uf2   = (float2*)(W3Rs + 512);   // [2 buf][2 mlp][64] float2 = 4KB

    int tid = threadIdx.x;
    int w = tid >> 5, l = tid & 31;
    int m  = w >> 2;       // 0 = diffusion (u), 1 = cnf (f)
    int wg = w & 3;        // sample group of 16
    int t3 = l & 3;        // quad thread
    int g  = l >> 2;       // row 0-7 (sample A); sample B = row g+8
    int blockBase = blockIdx.x * SPB;
    int gsA = blockBase + wg * 16 + g;
    int gsB = gsA + 8;

    // ================= phase 1 =================
    // 1) stage ctx tiles into the (not yet used) Bfrag regions
    {
        float* tD = (float*)BfD;
        float* tC = (float*)BfC;
        for (int idx = tid; idx < SPB * HID; idx += NTHREADS) {
            tD[idx] = pctx[(long long)blockBase * HID + idx];
            tC[idx] = cctx[(long long)blockBase * HID + idx];
        }
    }
    __syncthreads();
    // 2) base in old [s][k] layout: diffusion warps cover grp 0-7 for D, cnf for C
    if (m == 0) {
        compute_base(baseRD, (float*)BfD, dW1, wg * 2,     l);
        compute_base(baseRD, (float*)BfD, dW1, wg * 2 + 1, l);
    } else {
        compute_base(baseRC, (float*)BfC, cW1, wg * 2,     l);
        compute_base(baseRC, (float*)BfC, cW1, wg * 2 + 1, l);
    }
    __syncthreads();
    // 3) in-place permute base -> fragment order:
    //    ni = ((swg*8 + kt)*32 + lane)*8 + hi8*4 + comp
    {
        float tmpv[32];
#pragma unroll
        for (int a = 0; a < 2; a++) {
            float* arr = a ? baseRC : baseRD;
#pragma unroll
            for (int q = 0; q < 32; q++) tmpv[q] = arr[tid * 32 + q];
            __syncthreads();
#pragma unroll
            for (int q = 0; q < 32; q++) {
                int idx = tid * 32 + q;
                int s = idx >> 7, k = idx & 127;
                int swg = s >> 4, srow = s & 15;
                int hi8 = srow >> 3, gg = srow & 7;
                int kt = k >> 4, kr = k & 15;
                int lane = gg * 4 + ((kr & 7) >> 1);
                int ni = ((swg * 8 + kt) * 32 + lane) * 8 + hi8 * 4 + frag_comp(kr);
                arr[ni] = tmpv[q];
            }
            __syncthreads();
        }
    }
    // 4) W2 -> bf16 hi/lo in B-fragment layout; plus small tables
    {
        unsigned short* bD16 = (unsigned short*)BfD;
        unsigned short* bC16 = (unsigned short*)BfC;
        for (int e = tid; e < HID * HID; e += NTHREADS) {
            int k = e >> 7, j = e & 127;
            int kt = k >> 4, kr = k & 15;
            int reg = (kr >> 3) & 1, half = kr & 1;
            int lane = (j & 7) * 4 + ((kr & 7) >> 1);
            int ntg = j >> 3;
            int slot = (((kt * 16 + ntg) * 32 + lane) * 4);
            {
                float wv = dW2[e];
                __nv_bfloat16 hb = __float2bfloat16(wv);
                __nv_bfloat16 lb = __float2bfloat16(wv - __bfloat162float(hb));
                bD16[(slot + reg) * 2 + half]     = __bfloat16_as_ushort(hb);
                bD16[(slot + 2 + reg) * 2 + half] = __bfloat16_as_ushort(lb);
            }
            {
                float wv = cW2[e];
                __nv_bfloat16 hb = __float2bfloat16(wv);
                __nv_bfloat16 lb = __float2bfloat16(wv - __bfloat162float(hb));
                bC16[(slot + reg) * 2 + half]     = __bfloat16_as_ushort(hb);
                bC16[(slot + 2 + reg) * 2 + half] = __bfloat16_as_ushort(lb);
            }
        }
        // wzR: [mlp][row][kt][t][comp]
        for (int idx = tid; idx < 2 * 2 * HID; idx += NTHREADS) {
            int mlp = idx >> 8, row = (idx >> 7) & 1, k = idx & 127;
            int kt = k >> 4, kr = k & 15;
            float v = (mlp ? cW1 : dW1)[row * HID + k];
            wzRs[((mlp * 2 + row) * 8 + kt) * 16 + ((kr & 7) >> 1) * 4 + frag_comp(kr)] = v;
        }
        // b2R: [mlp][ntg][t][half]   (j = ntg*8 + 2t + half)
        for (int idx = tid; idx < 2 * HID; idx += NTHREADS) {
            int mlp = idx >> 7, j = idx & 127;
            float v = (mlp ? cb2 : db2)[j];
            b2Rs[(mlp * 16 + (j >> 3)) * 8 + ((j & 7) >> 1) * 2 + (j & 1)] = v;
        }
        // W3R: [mlp][ntg][t][(j&1)*2 + d]
        for (int idx = tid; idx < 2 * HID * ZD; idx += NTHREADS) {
            int mlp = idx >> 8, j = (idx >> 1) & 127, d = idx & 1;
            float v = (mlp ? cW3 : dW3)[j * ZD + d];
            W3Rs[(mlp * 16 + (j >> 3)) * 16 + ((j & 7) >> 1) * 4 + (j & 1) * 2 + d] = v;
        }
    }
    __syncthreads();

    // ================= per-warp constant pointers / regs =================
    const uint4*  Bf    = m ? BfC : BfD;
    const float4* bR4   = (const float4*)(m ? baseRC : baseRD);
    const float4* twR4  = (const float4*)(m ? g_twc : g_twd);
    const float4* wz04  = (const float4*)wzRs + (m * 2 + 0) * 32;
    const float4* wz14  = (const float4*)wzRs + (m * 2 + 1) * 32;
    const float2* b2R2  = (const float2*)b2Rs + m * 64;
    const float4* W3R4  = (const float4*)W3Rs + m * 64;
    const float2* noise2 = (const float2*)noise;
    float2* outTraj = (float2*)out;
    float2* outUS   = (float2*)(out + US_OFF);

    float b3_0, b3_1;
    { const float* b3 = m ? cb3 : db3; b3_0 = b3[0]; b3_1 = b3[1]; }

    // init z (all 4 lanes of quad hold both samples' z)
    float2 ziA = __ldg(&((const float2*)z0)[gsA]);
    float2 ziB = __ldg(&((const float2*)z0)[gsB]);
    float zA0 = ziA.x, zA1 = ziA.y, zB0 = ziB.x, zB1 = ziB.y;
    if (m == 1 && t3 == 0) { outTraj[gsA] = ziA; outTraj[gsB] = ziB; }

    // ================= 50-step loop =================
    for (int i = 0; i < NSTEPS; i++) {
        float dt = g_dts[i], cf = g_coef[i];
        long long io = (long long)i * N_SAMP;
        float2 xiA = __ldg(&noise2[io + gsA]);
        float2 xiB = __ldg(&noise2[io + gsB]);

        float d[16][4];
#pragma unroll
        for (int nt = 0; nt < 16; nt++)
#pragma unroll
            for (int c = 0; c < 4; c++) d[nt][c] = 0.f;

        // ---- fused layer-1 (A frags in regs) + tensor layer-2, per k-tile ----
#pragma unroll
        for (int kt = 0; kt < 8; kt++) {
            float4 bsA = bR4[((wg * 8 + kt) * 32 + l) * 2 + 0];
            float4 bsB = bR4[((wg * 8 + kt) * 32 + l) * 2 + 1];
            float4 tw  = __ldg(&twR4[i * 32 + kt * 4 + t3]);
            float4 w0  = wz04[kt * 4 + t3];
            float4 w1  = wz14[kt * 4 + t3];
            float hAx = fsilu(bsA.x + tw.x + zA0 * w0.x + zA1 * w1.x);
            float hAy = fsilu(bsA.y + tw.y + zA0 * w0.y + zA1 * w1.y);
            float hAz = fsilu(bsA.z + tw.z + zA0 * w0.z + zA1 * w1.z);
            float hAw = fsilu(bsA.w + tw.w + zA0 * w0.w + zA1 * w1.w);
            float hBx = fsilu(bsB.x + tw.x + zB0 * w0.x + zB1 * w1.x);
            float hBy = fsilu(bsB.y + tw.y + zB0 * w0.y + zB1 * w1.y);
            float hBz = fsilu(bsB.z + tw.z + zB0 * w0.z + zB1 * w1.z);
            float hBw = fsilu(bsB.w + tw.w + zB0 * w0.w + zB1 * w1.w);
            uint32_t a0h = cvt2bf(hAy, hAx);
            uint32_t a1h = cvt2bf(hBy, hBx);
            uint32_t a2h = cvt2bf(hAw, hAz);
            uint32_t a3h = cvt2bf(hBw, hBz);
            uint32_t a0l = cvt2bf(hAy - __uint_as_float(a0h & 0xffff0000u),
                                  hAx - __uint_as_float(a0h << 16));
            uint32_t a1l = cvt2bf(hBy - __uint_as_float(a1h & 0xffff0000u),
                                  hBx - __uint_as_float(a1h << 16));
            uint32_t a2l = cvt2bf(hAw - __uint_as_float(a2h & 0xffff0000u),
                                  hAz - __uint_as_float(a2h << 16));
            uint32_t a3l = cvt2bf(hBw - __uint_as_float(a3h & 0xffff0000u),
                                  hBz - __uint_as_float(a3h << 16));
#pragma unroll
            for (int ntc = 0; ntc < 16; ntc += 4) {
                uint4 Bv[4];
#pragma unroll
                for (int q = 0; q < 4; q++)
                    Bv[q] = Bf[(kt * 16 + ntc + q) * 32 + l];
#pragma unroll
                for (int q = 0; q < 4; q++)
                    mma16816(d[ntc + q], a0h, a1h, a2h, a3h, Bv[q].x, Bv[q].y);
#pragma unroll
                for (int q = 0; q < 4; q++)
                    mma16816(d[ntc + q], a0l, a1l, a2l, a3l, Bv[q].x, Bv[q].y);
#pragma unroll
                for (int q = 0; q < 4; q++)
                    mma16816(d[ntc + q], a0h, a1h, a2h, a3h, Bv[q].z, Bv[q].w);
            }
        }

        // ---- epilogue: silu(h2+b2), layer-3 partials (both samples) ----
        float aA0 = 0.f, aA1 = 0.f, aB0 = 0.f, aB1 = 0.f;
#pragma unroll
        for (int ntg = 0; ntg < 16; ntg++) {
            float2 b2v = b2R2[ntg * 4 + t3];
            float4 w3v = W3R4[ntg * 4 + t3];
            float x0 = fsilu(d[ntg][0] + b2v.x);
            float x1 = fsilu(d[ntg][1] + b2v.y);
            float x2 = fsilu(d[ntg][2] + b2v.x);
            float x3 = fsilu(d[ntg][3] + b2v.y);
            aA0 += x0 * w3v.x + x1 * w3v.z;
            aA1 += x0 * w3v.y + x1 * w3v.w;
            aB0 += x2 * w3v.x + x3 * w3v.z;
            aB1 += x2 * w3v.y + x3 * w3v.w;
        }

        // ---- quad reduction (all lanes get sums) ----
        aA0 += __shfl_xor_sync(0xffffffffu, aA0, 1);
        aA1 += __shfl_xor_sync(0xffffffffu, aA1, 1);
        aB0 += __shfl_xor_sync(0xffffffffu, aB0, 1);
        aB1 += __shfl_xor_sync(0xffffffffu, aB1, 1);
        aA0 += __shfl_xor_sync(0xffffffffu, aA0, 2);
        aA1 += __shfl_xor_sync(0xffffffffu, aA1, 2);
        aB0 += __shfl_xor_sync(0xffffffffu, aB0, 2);
        aB1 += __shfl_xor_sync(0xffffffffu, aB1, 2);
        float vA0 = aA0 + b3_0, vA1 = aA1 + b3_1;
        float vB0 = aB0 + b3_0, vB1 = aB1 + b3_1;

        // ---- cross-MLP exchange (double buffered, one barrier per step) ----
        int bufo = (i & 1) * 128;
        if (t3 == 0) {
            uf2[bufo + m * 64 + wg * 16 + g]     = make_float2(vA0, vA1);
            uf2[bufo + m * 64 + wg * 16 + g + 8] = make_float2(vB0, vB1);
        }
        __syncthreads();
        float2 ovA = uf2[bufo + (1 - m) * 64 + wg * 16 + g];
        float2 ovB = uf2[bufo + (1 - m) * 64 + wg * 16 + g + 8];

        zA0 += (vA0 + ovA.x) * dt + xiA.x * cf;
        zA1 += (vA1 + ovA.y) * dt + xiA.y * cf;
        zB0 += (vB0 + ovB.x) * dt + xiB.x * cf;
        zB1 += (vB1 + ovB.y) * dt + xiB.y * cf;
        if (t3 == 0) {
            if (m == 0) {
                outUS[io + gsA] = make_float2(vA0, vA1);
                outUS[io + gsB] = make_float2(vB0, vB1);
            } else {
                outTraj[(long long)(i + 1) * N_SAMP + gsA] = make_float2(zA0, zA1);
                outTraj[(long long)(i + 1) * N_SAMP + gsB] = make_float2(zB0, zB1);
            }
        }
    }
}

// ---------------------------------------------------------------------------
extern "C" void kernel_launch(void* const* d_in, const int* in_sizes, int n_in,
                              void* d_out, int out_size)
{
    const float* z0       = (const float*)d_in[0];
    const float* pctx     = (const float*)d_in[1];
    const float* cctx     = (const float*)d_in[2];
    const float* times    = (const float*)d_in[3];
    const float* noise    = (const float*)d_in[4];
    const float* freqs    = (const float*)d_in[5];
    const float* dW1      = (const float*)d_in[6];
    const float* db1      = (const float*)d_in[7];
    const float* dW2      = (const float*)d_in[8];
    const float* db2      = (const float*)d_in[9];
    const float* dW3      = (const float*)d_in[10];
    const float* db3      = (const float*)d_in[11];
    const float* cW1      = (const float*)d_in[12];
    const float* cb1      = (const float*)d_in[13];
    const float* cW2      = (const float*)d_in[14];
    const float* cb2      = (const float*)d_in[15];
    const float* cW3      = (const float*)d_in[16];
    const float* cb3      = (const float*)d_in[17];
    const float* log_diff = (const float*)d_in[18];
    float* out = (float*)d_out;

    // Bf 2*64KB + baseR 2*32KB + wzR 2KB + b2R 1KB + W3R 2KB + uf 4KB
    const int smemB = 2 * 65536 + 2 * 32768 + 512 * 4 + 256 * 4 + 512 * 4 + 512 * 8;
    cudaFuncSetAttribute(sde_kernel, cudaFuncAttributeMaxDynamicSharedMemorySize, smemB);

    prep_kernel<<<1, 128>>>(times, freqs, dW1, db1, cW1, cb1, log_diff, out);
    sde_kernel<<<N_SAMP / SPB, NTHREADS, smemB>>>(z0, pctx, cctx, noise,
                                                  dW1, dW2, db2, dW3, db3,
                                                  cW1, cW2, cb2, cW3, cb3, out);
}

// round 7
// speedup vs baseline: 2.3948x; 1.0015x over previous
#include <cuda_runtime.h>
#include <cuda_bf16.h>
#include <cstdint>

#define N_SAMP   262144
#define ZD       2
#define CTX      128
#define HID      128
#define TEMB     32
#define NSTEPS   50
#define SPB      64      // samples per block
#define NTHREADS 256     // 8 warps: 4 diffusion + 4 cnf, 16 samples each

// output layout: traj [51,N,2] | us [50,N,2] | times [51]
#define US_OFF    ((long long)(NSTEPS+1) * N_SAMP * ZD)
#define TAIL_OFF  (US_OFF + (long long)NSTEPS * N_SAMP * ZD)

// per-step constants, tw permuted into per-lane fragment order:
// idx = i*128 + kt*16 + t*4 + comp,  comp = reg*2 + half  (k = kt*16 + 2t + reg*8 + half)
__device__ float g_twd[NSTEPS * HID];
__device__ float g_twc[NSTEPS * HID];
__device__ float g_dts[NSTEPS];
__device__ float g_coef[NSTEPS];

// fast silu: x*sigmoid(x) = 0.5x + 0.5x*tanh(0.5x)  (1 MUFU.TANH)
__device__ __forceinline__ float fsilu(float x) {
    float h = 0.5f * x;
    float t;
    asm("tanh.approx.f32 %0, %1;" : "=f"(t) : "f"(h));
    return fmaf(h, t, h);
}
// pack: lower half = even-k val, upper half = odd-k val
__device__ __forceinline__ uint32_t cvt2bf(float odd_k, float even_k) {
    uint32_t r; asm("cvt.rn.bf16x2.f32 %0, %1, %2;" : "=r"(r) : "f"(odd_k), "f"(even_k)); return r;
}
__device__ __forceinline__ void mma16816(float* d, uint32_t a0, uint32_t a1,
                                         uint32_t a2, uint32_t a3,
                                         uint32_t b0, uint32_t b1) {
    asm volatile("mma.sync.aligned.m16n8k16.row.col.f32.bf16.bf16.f32 "
                 "{%0,%1,%2,%3}, {%4,%5,%6,%7}, {%8,%9}, {%0,%1,%2,%3};"
                 : "+f"(d[0]), "+f"(d[1]), "+f"(d[2]), "+f"(d[3])
                 : "r"(a0), "r"(a1), "r"(a2), "r"(a3), "r"(b0), "r"(b1));
}

// fragment position helpers (k within 128): kt = k>>4, kr = k&15
// t = (kr&7)>>1, reg = (kr>>3)&1, half = kr&1, comp = reg*2 + half
__host__ __device__ __forceinline__ int frag_comp(int kr) { return (((kr >> 3) & 1) << 1) | (kr & 1); }

// ---------------------------------------------------------------------------
// Kernel A: per-step constants (temb @ W1_temb + b1 in permuted layout) + times tail
// ---------------------------------------------------------------------------
__global__ void prep_kernel(const float* __restrict__ times,
                            const float* __restrict__ freqs,
                            const float* __restrict__ dW1, const float* __restrict__ db1,
                            const float* __restrict__ cW1, const float* __restrict__ cb1,
                            const float* __restrict__ log_diff,
                            float* __restrict__ out)
{
    __shared__ float temb[TEMB];
    int tid = threadIdx.x;  // 128 threads, tid = k
    if (tid < NSTEPS + 1) out[TAIL_OFF + tid] = times[tid];
    int kt = tid >> 4, kr = tid & 15;
    int pidx = kt * 16 + ((kr & 7) >> 1) * 4 + frag_comp(kr);  // permuted position
    float gb = log1pf(__expf(log_diff[0]));  // softplus
    for (int i = 0; i < NSTEPS; i++) {
        float t = times[i];
        __syncthreads();
        if (tid < TEMB / 2) {
            float a = 6.2831853071795864f * t * freqs[tid];
            temb[tid]            = sinf(a);
            temb[tid + TEMB / 2] = cosf(a);
        }
        __syncthreads();
        float ad = db1[tid], ac = cb1[tid];
#pragma unroll 8
        for (int mm = 0; mm < TEMB; mm++) {
            float tv = temb[mm];
            ad += tv * dW1[(ZD + CTX + mm) * HID + tid];
            ac += tv * cW1[(ZD + CTX + mm) * HID + tid];
        }
        g_twd[i * HID + pidx] = ad;
        g_twc[i * HID + pidx] = ac;
        if (tid == 0) {
            float dt = times[i + 1] - t;
            g_dts[i]  = dt;
            g_coef[i] = gb * (1.0f - t) * sqrtf(fmaxf(dt, 1e-12f));
        }
    }
}

// ---------------------------------------------------------------------------
// base = ctx @ W1[2:130] for one group of 8 samples (old [s][k] layout)
// ---------------------------------------------------------------------------
__device__ __forceinline__ void compute_base(float* __restrict__ dst,
                                             const float* __restrict__ tmp,
                                             const float* __restrict__ W1,
                                             int grp, int l)
{
    float acc[8][4];
#pragma unroll
    for (int s8 = 0; s8 < 8; s8++)
#pragma unroll
        for (int c = 0; c < 4; c++) acc[s8][c] = 0.f;
#pragma unroll 2
    for (int r = 0; r < CTX; r++) {
        float w1v[4];
#pragma unroll
        for (int c = 0; c < 4; c++) w1v[c] = W1[(ZD + r) * HID + l + 32 * c];
#pragma unroll
        for (int s8 = 0; s8 < 8; s8++) {
            float a = tmp[(grp * 8 + s8) * HID + r];
#pragma unroll
            for (int c = 0; c < 4; c++) acc[s8][c] += a * w1v[c];
        }
    }
#pragma unroll
    for (int s8 = 0; s8 < 8; s8++)
#pragma unroll
        for (int c = 0; c < 4; c++)
            dst[(grp * 8 + s8) * HID + l + 32 * c] = acc[s8][c];
}

// ---------------------------------------------------------------------------
// Kernel B: persistent 50-step SDE, tensor-core layer-2, 16 REAL samples/warp.
// 256 threads: warps 0-3 diffusion MLP, warps 4-7 cnf MLP, 16 samples/warp.
// SMEM: BfD(64K) BfC(64K) baseRD(32K) baseRC(32K) + tables + uf ≈ 201KB.
// ---------------------------------------------------------------------------
__global__ void __launch_bounds__(NTHREADS, 1)
sde_kernel(const float* __restrict__ z0,
           const float* __restrict__ pctx, const float* __restrict__ cctx,
           const float* __restrict__ noise,
           const float* __restrict__ dW1, const float* __restrict__ dW2,
           const float* __restrict__ db2, const float* __restrict__ dW3,
           const float* __restrict__ db3,
           const float* __restrict__ cW1, const float* __restrict__ cW2,
           const float* __restrict__ cb2, const float* __restrict__ cW3,
           const float* __restrict__ cb3,
           float* __restrict__ out)
{
    extern __shared__ float sm[];
    uint4* BfD    = (uint4*)sm;              // 8kt*16ntg*32lane uint4 = 64KB
    uint4* BfC    = BfD + 4096;              // 64KB
    float* baseRD = (float*)(BfC + 4096);    // 4 wg * 2048 floats = 32KB
    float* baseRC = baseRD + 8192;           // 32KB
    float* wzRs   = baseRC + 8192;           // [mlp][row][kt][t] float4 = 512 f
    float* b2Rs   = wzRs + 512;              // [mlp][ntg][t] float2 = 256 f
    float* W3Rs   = b2Rs + 256;              // [mlp][ntg][t] float4 = 512 f
    float2* uf2   = (float2*)(W3Rs + 512);   // [2 buf][2 mlp][64] float2 = 4KB

    int tid = threadIdx.x;
    int w = tid >> 5, l = tid & 31;
    int m  = w >> 2;       // 0 = diffusion (u), 1 = cnf (f)
    int wg = w & 3;        // sample group of 16
    int t3 = l & 3;        // quad thread
    int g  = l >> 2;       // row 0-7 (sample A); sample B = row g+8
    int blockBase = blockIdx.x * SPB;
    int gsA = blockBase + wg * 16 + g;
    int gsB = gsA + 8;

    // ================= phase 1 =================
    // 1) stage ctx tiles into the (not yet used) Bfrag regions
    {
        float* tD = (float*)BfD;
        float* tC = (float*)BfC;
        for (int idx = tid; idx < SPB * HID; idx += NTHREADS) {
            tD[idx] = pctx[(long long)blockBase * HID + idx];
            tC[idx] = cctx[(long long)blockBase * HID + idx];
        }
    }
    __syncthreads();
    // 2) base in old [s][k] layout: diffusion warps cover grp 0-7 for D, cnf for C
    if (m == 0) {
        compute_base(baseRD, (float*)BfD, dW1, wg * 2,     l);
        compute_base(baseRD, (float*)BfD, dW1, wg * 2 + 1, l);
    } else {
        compute_base(baseRC, (float*)BfC, cW1, wg * 2,     l);
        compute_base(baseRC, (float*)BfC, cW1, wg * 2 + 1, l);
    }
    __syncthreads();
    // 3) in-place permute base -> fragment order:
    //    ni = ((swg*8 + kt)*32 + lane)*8 + hi8*4 + comp
    {
        float tmpv[32];
#pragma unroll
        for (int a = 0; a < 2; a++) {
            float* arr = a ? baseRC : baseRD;
#pragma unroll
            for (int q = 0; q < 32; q++) tmpv[q] = arr[tid * 32 + q];
            __syncthreads();
#pragma unroll
            for (int q = 0; q < 32; q++) {
                int idx = tid * 32 + q;
                int s = idx >> 7, k = idx & 127;
                int swg = s >> 4, srow = s & 15;
                int hi8 = srow >> 3, gg = srow & 7;
                int kt = k >> 4, kr = k & 15;
                int lane = gg * 4 + ((kr & 7) >> 1);
                int ni = ((swg * 8 + kt) * 32 + lane) * 8 + hi8 * 4 + frag_comp(kr);
                arr[ni] = tmpv[q];
            }
            __syncthreads();
        }
    }
    // 4) W2 -> bf16 hi/lo in B-fragment layout; plus small tables
    {
        unsigned short* bD16 = (unsigned short*)BfD;
        unsigned short* bC16 = (unsigned short*)BfC;
        for (int e = tid; e < HID * HID; e += NTHREADS) {
            int k = e >> 7, j = e & 127;
            int kt = k >> 4, kr = k & 15;
            int reg = (kr >> 3) & 1, half = kr & 1;
            int lane = (j & 7) * 4 + ((kr & 7) >> 1);
            int ntg = j >> 3;
            int slot = (((kt * 16 + ntg) * 32 + lane) * 4);
            {
                float wv = dW2[e];
                __nv_bfloat16 hb = __float2bfloat16(wv);
                __nv_bfloat16 lb = __float2bfloat16(wv - __bfloat162float(hb));
                bD16[(slot + reg) * 2 + half]     = __bfloat16_as_ushort(hb);
                bD16[(slot + 2 + reg) * 2 + half] = __bfloat16_as_ushort(lb);
            }
            {
                float wv = cW2[e];
                __nv_bfloat16 hb = __float2bfloat16(wv);
                __nv_bfloat16 lb = __float2bfloat16(wv - __bfloat162float(hb));
                bC16[(slot + reg) * 2 + half]     = __bfloat16_as_ushort(hb);
                bC16[(slot + 2 + reg) * 2 + half] = __bfloat16_as_ushort(lb);
            }
        }
        // wzR: [mlp][row][kt][t][comp]
        for (int idx = tid; idx < 2 * 2 * HID; idx += NTHREADS) {
            int mlp = idx >> 8, row = (idx >> 7) & 1, k = idx & 127;
            int kt = k >> 4, kr = k & 15;
            float v = (mlp ? cW1 : dW1)[row * HID + k];
            wzRs[((mlp * 2 + row) * 8 + kt) * 16 + ((kr & 7) >> 1) * 4 + frag_comp(kr)] = v;
        }
        // b2R: [mlp][ntg][t][half]   (j = ntg*8 + 2t + half)
        for (int idx = tid; idx < 2 * HID; idx += NTHREADS) {
            int mlp = idx >> 7, j = idx & 127;
            float v = (mlp ? cb2 : db2)[j];
            b2Rs[(mlp * 16 + (j >> 3)) * 8 + ((j & 7) >> 1) * 2 + (j & 1)] = v;
        }
        // W3R: [mlp][ntg][t][(j&1)*2 + d]
        for (int idx = tid; idx < 2 * HID * ZD; idx += NTHREADS) {
            int mlp = idx >> 8, j = (idx >> 1) & 127, d = idx & 1;
            float v = (mlp ? cW3 : dW3)[j * ZD + d];
            W3Rs[(mlp * 16 + (j >> 3)) * 16 + ((j & 7) >> 1) * 4 + (j & 1) * 2 + d] = v;
        }
    }
    __syncthreads();

    // ================= per-warp constant pointers / regs =================
    const uint4*  Bf    = m ? BfC : BfD;
    const float4* bR4   = (const float4*)(m ? baseRC : baseRD);
    const float4* twR4  = (const float4*)(m ? g_twc : g_twd);
    const float4* wz04  = (const float4*)wzRs + (m * 2 + 0) * 32;
    const float4* wz14  = (const float4*)wzRs + (m * 2 + 1) * 32;
    const float2* b2R2  = (const float2*)b2Rs + m * 64;
    const float4* W3R4  = (const float4*)W3Rs + m * 64;
    const float2* noise2 = (const float2*)noise;
    float2* outTraj = (float2*)out;
    float2* outUS   = (float2*)(out + US_OFF);

    float b3_0, b3_1;
    { const float* b3 = m ? cb3 : db3; b3_0 = b3[0]; b3_1 = b3[1]; }

    // init z (all 4 lanes of quad hold both samples' z)
    float2 ziA = __ldg(&((const float2*)z0)[gsA]);
    float2 ziB = __ldg(&((const float2*)z0)[gsB]);
    float zA0 = ziA.x, zA1 = ziA.y, zB0 = ziB.x, zB1 = ziB.y;
    if (m == 1 && t3 == 0) { outTraj[gsA] = ziA; outTraj[gsB] = ziB; }

    // ================= 50-step loop =================
    for (int i = 0; i < NSTEPS; i++) {
        float dt = g_dts[i], cf = g_coef[i];
        long long io = (long long)i * N_SAMP;
        float2 xiA = __ldg(&noise2[io + gsA]);
        float2 xiB = __ldg(&noise2[io + gsB]);

        float d[16][4];
#pragma unroll
        for (int nt = 0; nt < 16; nt++)
#pragma unroll
            for (int c = 0; c < 4; c++) d[nt][c] = 0.f;

        // ---- fused layer-1 (A frags in regs) + tensor layer-2, per k-tile ----
#pragma unroll
        for (int kt = 0; kt < 8; kt++) {
            float4 bsA = bR4[((wg * 8 + kt) * 32 + l) * 2 + 0];
            float4 bsB = bR4[((wg * 8 + kt) * 32 + l) * 2 + 1];
            float4 tw  = __ldg(&twR4[i * 32 + kt * 4 + t3]);
            float4 w0  = wz04[kt * 4 + t3];
            float4 w1  = wz14[kt * 4 + t3];
            float hAx = fsilu(bsA.x + tw.x + zA0 * w0.x + zA1 * w1.x);
            float hAy = fsilu(bsA.y + tw.y + zA0 * w0.y + zA1 * w1.y);
            float hAz = fsilu(bsA.z + tw.z + zA0 * w0.z + zA1 * w1.z);
            float hAw = fsilu(bsA.w + tw.w + zA0 * w0.w + zA1 * w1.w);
            float hBx = fsilu(bsB.x + tw.x + zB0 * w0.x + zB1 * w1.x);
            float hBy = fsilu(bsB.y + tw.y + zB0 * w0.y + zB1 * w1.y);
            float hBz = fsilu(bsB.z + tw.z + zB0 * w0.z + zB1 * w1.z);
            float hBw = fsilu(bsB.w + tw.w + zB0 * w0.w + zB1 * w1.w);
            uint32_t a0h = cvt2bf(hAy, hAx);
            uint32_t a1h = cvt2bf(hBy, hBx);
            uint32_t a2h = cvt2bf(hAw, hAz);
            uint32_t a3h = cvt2bf(hBw, hBz);
            uint32_t a0l = cvt2bf(hAy - __uint_as_float(a0h & 0xffff0000u),
                                  hAx - __uint_as_float(a0h << 16));
            uint32_t a1l = cvt2bf(hBy - __uint_as_float(a1h & 0xffff0000u),
                                  hBx - __uint_as_float(a1h << 16));
            uint32_t a2l = cvt2bf(hAw - __uint_as_float(a2h & 0xffff0000u),
                                  hAz - __uint_as_float(a2h << 16));
            uint32_t a3l = cvt2bf(hBw - __uint_as_float(a3h & 0xffff0000u),
                                  hBz - __uint_as_float(a3h << 16));
#pragma unroll
            for (int ntc = 0; ntc < 16; ntc += 4) {
                uint4 Bv[4];
#pragma unroll
                for (int q = 0; q < 4; q++)
                    Bv[q] = Bf[(kt * 16 + ntc + q) * 32 + l];
#pragma unroll
                for (int q = 0; q < 4; q++)
                    mma16816(d[ntc + q], a0h, a1h, a2h, a3h, Bv[q].x, Bv[q].y);
#pragma unroll
                for (int q = 0; q < 4; q++)
                    mma16816(d[ntc + q], a0l, a1l, a2l, a3l, Bv[q].x, Bv[q].y);
#pragma unroll
                for (int q = 0; q < 4; q++)
                    mma16816(d[ntc + q], a0h, a1h, a2h, a3h, Bv[q].z, Bv[q].w);
            }
        }

        // ---- epilogue: silu(h2+b2), layer-3 partials (both samples) ----
        float aA0 = 0.f, aA1 = 0.f, aB0 = 0.f, aB1 = 0.f;
#pragma unroll
        for (int ntg = 0; ntg < 16; ntg++) {
            float2 b2v = b2R2[ntg * 4 + t3];
            float4 w3v = W3R4[ntg * 4 + t3];
            float x0 = fsilu(d[ntg][0] + b2v.x);
            float x1 = fsilu(d[ntg][1] + b2v.y);
            float x2 = fsilu(d[ntg][2] + b2v.x);
            float x3 = fsilu(d[ntg][3] + b2v.y);
            aA0 += x0 * w3v.x + x1 * w3v.z;
            aA1 += x0 * w3v.y + x1 * w3v.w;
            aB0 += x2 * w3v.x + x3 * w3v.z;
            aB1 += x2 * w3v.y + x3 * w3v.w;
        }

        // ---- quad reduction (all lanes get sums) ----
        aA0 += __shfl_xor_sync(0xffffffffu, aA0, 1);
        aA1 += __shfl_xor_sync(0xffffffffu, aA1, 1);
        aB0 += __shfl_xor_sync(0xffffffffu, aB0, 1);
        aB1 += __shfl_xor_sync(0xffffffffu, aB1, 1);
        aA0 += __shfl_xor_sync(0xffffffffu, aA0, 2);
        aA1 += __shfl_xor_sync(0xffffffffu, aA1, 2);
        aB0 += __shfl_xor_sync(0xffffffffu, aB0, 2);
        aB1 += __shfl_xor_sync(0xffffffffu, aB1, 2);
        float vA0 = aA0 + b3_0, vA1 = aA1 + b3_1;
        float vB0 = aB0 + b3_0, vB1 = aB1 + b3_1;

        // ---- cross-MLP exchange (double buffered, one barrier per step) ----
        int bufo = (i & 1) * 128;
        if (t3 == 0) {
            uf2[bufo + m * 64 + wg * 16 + g]     = make_float2(vA0, vA1);
            uf2[bufo + m * 64 + wg * 16 + g + 8] = make_float2(vB0, vB1);
        }
        __syncthreads();
        float2 ovA = uf2[bufo + (1 - m) * 64 + wg * 16 + g];
        float2 ovB = uf2[bufo + (1 - m) * 64 + wg * 16 + g + 8];

        zA0 += (vA0 + ovA.x) * dt + xiA.x * cf;
        zA1 += (vA1 + ovA.y) * dt + xiA.y * cf;
        zB0 += (vB0 + ovB.x) * dt + xiB.x * cf;
        zB1 += (vB1 + ovB.y) * dt + xiB.y * cf;
        if (t3 == 0) {
            if (m == 0) {
                outUS[io + gsA] = make_float2(vA0, vA1);
                outUS[io + gsB] = make_float2(vB0, vB1);
            } else {
                outTraj[(long long)(i + 1) * N_SAMP + gsA] = make_float2(zA0, zA1);
                outTraj[(long long)(i + 1) * N_SAMP + gsB] = make_float2(zB0, zB1);
            }
        }
    }
}

// ---------------------------------------------------------------------------
extern "C" void kernel_launch(void* const* d_in, const int* in_sizes, int n_in,
                              void* d_out, int out_size)
{
    const float* z0       = (const float*)d_in[0];
    const float* pctx     = (const float*)d_in[1];
    const float* cctx     = (const float*)d_in[2];
    const float* times    = (const float*)d_in[3];
    const float* noise    = (const float*)d_in[4];
    const float* freqs    = (const float*)d_in[5];
    const float* dW1      = (const float*)d_in[6];
    const float* db1      = (const float*)d_in[7];
    const float* dW2      = (const float*)d_in[8];
    const float* db2      = (const float*)d_in[9];
    const float* dW3      = (const float*)d_in[10];
    const float* db3      = (const float*)d_in[11];
    const float* cW1      = (const float*)d_in[12];
    const float* cb1      = (const float*)d_in[13];
    const float* cW2      = (const float*)d_in[14];
    const float* cb2      = (const float*)d_in[15];
    const float* cW3      = (const float*)d_in[16];
    const float* cb3      = (const float*)d_in[17];
    const float* log_diff = (const float*)d_in[18];
    float* out = (float*)d_out;

    // Bf 2*64KB + baseR 2*32KB + wzR 2KB + b2R 1KB + W3R 2KB + uf 4KB
    const int smemB = 2 * 65536 + 2 * 32768 + 512 * 4 + 256 * 4 + 512 * 4 + 512 * 8;
    cudaFuncSetAttribute(sde_kernel, cudaFuncAttributeMaxDynamicSharedMemorySize, smemB);

    prep_kernel<<<1, 128>>>(times, freqs, dW1, db1, cW1, cb1, log_diff, out);
    sde_kernel<<<N_SAMP / SPB, NTHREADS, smemB>>>(z0, pctx, cctx, noise,
                                                  dW1, dW2, db2, dW3, db3,
                                                  cW1, cW2, cb2, cW3, cb3, out);
}